// round 16
// baseline (speedup 1.0000x reference)
#include <cuda_runtime.h>
#include <cuda_bf16.h>

// PatchShuffle: T=1024 (16 rows x 64 cols), B=64, C=768, STRIPE_W=48.
// Outputs concatenated as float32:
//   visible       [256*64*768]   gather of shuffled rows 0..255
//   fwd           [1024*64]      forward permutation (as float)
//   bwd           [1024*64]      inverse permutation (as float)
//   stripe_bounds [2*64]         {start, start+48} per batch
//
// perm(b, j):  s = start[b]
//   j <  s        -> j
//   s <= j < 16   -> j + 48
//   j >= 16       -> s + (j-16)
// inverse:
//   col <  s        -> col
//   s <= col < s+48 -> 16 + (col - s)
//   col >= s+48     -> col - 48
//
// SCHEDULING CONTRACT (measured R3/R5/R6/R9/R12/R13):
//  * Front-batched LDG.128 at full residency -> cross-CTA L1tex contention
//    (21us). Occupancy cap -> TLP starvation (17us). Winning shape = full
//    occupancy + MLP_p1=2, forced deterministically: patches/out NOT
//    __restrict__, stores interleaved between load pairs. 13.05us. PROTECTED.
//  * STORE POLICY (this round): warm replays are DRAM-write-bound
//    (48.5MB / 13.0us = 3.73TB/s = measured HBM rate). Split policy:
//    output bytes [0, 24.2MB) default writeback (stays L2-resident across
//    replays, resident set 48+24.2=72MB < 126MB L2), rest __stcs streamed.
//    Halves DRAM write traffic per replay.

#define STRIPE_W   48
#define B_         64
#define C_         768
#define C4_        192
#define T_VIS      256
#define T_ALL      1024

#define N_VIS4     (T_VIS * B_ * C4_)        // 3,145,728 float4
#define OFF_FWD    (T_VIS * B_ * C_)         // 12,582,912 floats
#define N_FWD      (T_ALL * B_)              // 65,536
#define OFF_BWD    (OFF_FWD + N_FWD)
#define OFF_SB     (OFF_BWD + N_FWD)

#define ILP        4
#define THREADS    256
#define VIS_STRIDE (N_VIS4 / ILP)            // 786,432 = 4096*192
#define VIS_BLOCKS (VIS_STRIDE / THREADS)    // 3072 exactly
#define SRC_STEP   (64 * B_ * C4_)           // 786,432 float4 (t += 64 step)

#define N_TAIL     (2 * N_FWD + 128)         // 131,200
#define TAIL_BLOCKS ((N_TAIL + THREADS - 1) / THREADS)  // 513 (folded)

__device__ __forceinline__ int perm_of(int s, int j) {
    return (j < s) ? j : ((j < 16) ? (j + STRIPE_W) : (s + (j - 16)));
}

__device__ __forceinline__ int inv_of(int s, int col) {
    return (col < s) ? col : ((col < s + STRIPE_W) ? (16 + (col - s)) : (col - STRIPE_W));
}

__global__ void __launch_bounds__(THREADS)
patchshuffle_kernel(const float4* patches,          // intentionally NOT __restrict__
                    const int*    __restrict__ start_cols,
                    float*        out) {            // intentionally NOT __restrict__
    int bid = blockIdx.x;
    int tid = threadIdx.x;

    // ---- visible gather: 4 items/thread at stride 786,432 ----
    // c4, b, t0 invariant across items; item m is row=m:
    // src_m = src0 + m*SRC_STEP, dst_m = base + m*VIS_STRIDE.
    {
        int base  = bid * THREADS + tid;
        int c4    = base % C4_;
        int pair0 = base / C4_;              // in [0, 4096)
        int b     = pair0 & 63;
        int t0    = pair0 >> 6;              // in [0, 64) == j for ALL items
        int s     = __ldg(start_cols + b);
        int p     = perm_of(s, t0);          // computed ONCE

        const float4* src = patches + (p * B_ + b) * C4_ + c4;
        float4*       dst = reinterpret_cast<float4*>(out) + base;

        // Pairwise load/store interleave (forced MLP_p1=2 — do not reorder).
        // Items 0,1 -> output bytes [0, 24.2MB): default writeback (L2-resident
        // across replays). Items 2,3 -> streamed to DRAM (evict-first).
        float4 v0 = src[0 * SRC_STEP];
        float4 v1 = src[1 * SRC_STEP];
        dst[0 * VIS_STRIDE] = v0;                      // writeback half
        dst[1 * VIS_STRIDE] = v1;                      // writeback half
        float4 v2 = src[2 * SRC_STEP];
        float4 v3 = src[3 * SRC_STEP];
        __stcs(dst + 2 * VIS_STRIDE, v2);              // streamed half
        __stcs(dst + 3 * VIS_STRIDE, v3);              // streamed half
    }

    // ---- tail folded into the first 513 blocks (streamed) ----
    if (bid < TAIL_BLOCKS) {
        int r = bid * THREADS + tid;
        if (r < N_FWD) {
            // fwd[t][b]
            int t   = r >> 6;
            int b   = r & 63;
            int row = t >> 6;
            int j   = t & 63;
            int s   = __ldg(start_cols + b);
            __stcs(out + OFF_FWD + r, (float)((row << 6) + perm_of(s, j)));
            return;
        }
        r -= N_FWD;
        if (r < N_FWD) {
            // bwd[i][b]
            int i   = r >> 6;
            int b   = r & 63;
            int row = i >> 6;
            int col = i & 63;
            int s   = __ldg(start_cols + b);
            __stcs(out + OFF_BWD + r, (float)((row << 6) + inv_of(s, col)));
            return;
        }
        r -= N_FWD;
        if (r < 128) {
            // stripe_bounds[2][64]
            int b = r & 63;
            int s = __ldg(start_cols + b);
            __stcs(out + OFF_SB + r, (float)((r < 64) ? s : (s + STRIPE_W)));
        }
    }
}

extern "C" void kernel_launch(void* const* d_in, const int* in_sizes, int n_in,
                              void* d_out, int out_size) {
    const float4* patches    = (const float4*)d_in[0];
    const int*    start_cols = (const int*)d_in[1];
    float*        out        = (float*)d_out;

    patchshuffle_kernel<<<VIS_BLOCKS, THREADS>>>(patches, start_cols, out);
}